// round 1
// baseline (speedup 1.0000x reference)
#include <cuda_runtime.h>
#include <cstdint>

#define T_ 128
#define B_ 32
#define I_ 128
#define H_ 320
#define O_ 32
#define G_ 8
#define HP 80            // hidden rows per CTA (H/4)
#define NTHR 320
#define AX 0.2f          // ALPHA_X
#define AW 0.1f          // ALPHA_W
#define KW 0.9f          // 1 - ALPHA_W
#define SIGNB 256        // sign flips / exist cutoff at 256

// ---- shared memory layout (float offsets) ----
#define OFF_WX    0        // 80*128 = 10240
#define OFF_WH    10240    // 80*320 = 25600
#define OFF_BUF   35840    // 3*320  = 960   (output ring buffer, replicated per CTA)
#define OFF_OUTS  36800    // 320    (sign-applied old output)
#define OFF_XM    37120    // 128
#define OFF_A     37248    // 128
#define OFF_B     37376    // 128
#define OFF_C     37504    // 320
#define OFF_D     37824    // 320
#define OFF_NOS   38144    // 80     (new output, local rows)
#define OFF_ST    38224    // 80     (state, local rows)
#define OFF_BH    38304    // 80     (b_h2h chunk)
#define OFF_EA    38384    // 8*320 = 2560 (masked relu(W_attn))
#define OFF_LG    40944    // 8
#define OFF_AT    40952    // 8
#define OFF_BA    40960    // 8
#define OFF_CB    40968    // 8
#define SMEM_FLOATS 40976
#define SMEM_BYTES (SMEM_FLOATS * 4)

__device__ __forceinline__ uint32_t smem_u32(const void* p) {
    return (uint32_t)__cvta_generic_to_shared(p);
}
__device__ __forceinline__ void st_cluster_f32(uint32_t addr, uint32_t rank, float v) {
    uint32_t ra;
    asm volatile("mapa.shared::cluster.u32 %0, %1, %2;" : "=r"(ra) : "r"(addr), "r"(rank));
    asm volatile("st.shared::cluster.f32 [%0], %1;" :: "r"(ra), "f"(v) : "memory");
}
#define CLUSTER_SYNC() do { \
    asm volatile("barrier.cluster.arrive.aligned;" ::: "memory"); \
    asm volatile("barrier.cluster.wait.aligned;"   ::: "memory"); } while (0)

__device__ __forceinline__ float dot4r(float4 w, float4 v) {
    return fmaxf(w.x, 0.f) * v.x + fmaxf(w.y, 0.f) * v.y +
           fmaxf(w.z, 0.f) * v.z + fmaxf(w.w, 0.f) * v.w;
}

__global__ void __launch_bounds__(NTHR, 1)
rnn_kernel(const float* __restrict__ x, const float* __restrict__ Rs,
           const float* __restrict__ W_x2h, const float* __restrict__ W_h2h,
           const float* __restrict__ b_h2h, const float* __restrict__ W_attn,
           const float* __restrict__ b_attn, const float* __restrict__ c_plas,
           float* __restrict__ hs)
{
    extern __shared__ float sm[];
    float* wx   = sm + OFF_WX;
    float* wh   = sm + OFF_WH;
    float* buf  = sm + OFF_BUF;
    float* outs = sm + OFF_OUTS;
    float* xm   = sm + OFF_XM;
    float* Aa   = sm + OFF_A;
    float* Bb   = sm + OFF_B;
    float* Cc   = sm + OFF_C;
    float* Dd   = sm + OFF_D;
    float* nos  = sm + OFF_NOS;
    float* st   = sm + OFF_ST;
    float* bh   = sm + OFF_BH;
    float* ea   = sm + OFF_EA;
    float* lg   = sm + OFF_LG;
    float* at   = sm + OFF_AT;
    float* ba   = sm + OFF_BA;
    float* cb   = sm + OFF_CB;

    const int tid  = threadIdx.x;
    const int lane = tid & 31;
    const int wid  = tid >> 5;
    uint32_t rank; asm("mov.u32 %0, %%cluster_ctarank;" : "=r"(rank));
    const int b  = blockIdx.x >> 2;
    const int r0 = (int)rank * HP;

    // ---------------- init: load plastic weights + constants into SMEM -------------
    #pragma unroll
    for (int k = 0; k < 32; k++) {             // wx: 10240 floats, relu, mask_x = 1
        int f = tid + k * NTHR;
        int rg = r0 + (f >> 7);
        int c  = f & 127;
        wx[f] = fmaxf(W_x2h[rg * I_ + c], 0.f);
    }
    #pragma unroll
    for (int k = 0; k < 80; k++) {             // wh: relu * sign * (1 - eye)
        int f = k * NTHR + tid;                // row = k (local), col = tid
        int rg = r0 + k;
        float v = fmaxf(W_h2h[rg * H_ + tid], 0.f);
        v = (tid < SIGNB) ? v : -v;
        if (rg == tid) v = 0.f;
        wh[f] = v;
    }
    #pragma unroll
    for (int k = 0; k < 8; k++) {              // ew_attn = relu(W_attn) * mask_a
        ea[k * H_ + tid] = (tid < SIGNB) ? fmaxf(W_attn[k * H_ + tid], 0.f) : 0.f;
    }
    if (tid < HP) { st[tid] = 0.f; bh[tid] = b_h2h[r0 + tid]; }
    buf[tid] = 0.f; buf[tid + H_] = 0.f; buf[tid + 2 * H_] = 0.f;
    if (tid < 8) ba[tid] = b_attn[tid];
    if (tid < 6) cb[tid] = fabsf(c_plas[tid]);
    __syncthreads();
    CLUSTER_SYNC();

    // ---------------- time loop ----------------
    for (int t = 0; t < T_; t++) {
        float* oldb = buf + (t % 3) * H_;
        float* newb = buf + ((t + 1) % 3) * H_;

        // phase 1a: attention logits (warps 0..7) + outs/C/D (all threads)
        if (wid < 8) {
            float s = 0.f;
            #pragma unroll
            for (int k2 = 0; k2 < 8; k2++) {   // only first 256 cols nonzero
                int j = lane + 32 * k2;
                s += ea[wid * H_ + j] * oldb[j];
            }
            #pragma unroll
            for (int o = 16; o; o >>= 1) s += __shfl_xor_sync(0xffffffffu, s, o);
            if (lane == 0) lg[wid] = s + ba[wid];
        }
        const float R   = __ldg(&Rs[t * B_ + b]);
        const float awR = AW * R;
        {
            float oj = oldb[tid];
            outs[tid] = (tid < SIGNB) ? oj : -oj;
            Cc[tid] = awR * cb[3] * oj;
            Dd[tid] = awR * (cb[4] + cb[5] * oj);
        }
        __syncthreads();

        // phase 1b: softmax over G=8 (warp 0, lanes 0..7)
        if (wid == 0 && lane < 8) {
            float v = lg[lane];
            float m = v;
            #pragma unroll
            for (int o = 4; o; o >>= 1) m = fmaxf(m, __shfl_xor_sync(0xffu, m, o));
            float e = expf(v - m);
            float s2 = e;
            #pragma unroll
            for (int o = 4; o; o >>= 1) s2 += __shfl_xor_sync(0xffu, s2, o);
            at[lane] = e / s2;
        }
        __syncthreads();

        // phase 1c: xm + per-column wx-update coefficients
        if (tid < I_) {
            float xv = x[(t * B_ + b) * I_ + tid] * at[tid >> 4] * (float)G_;
            xm[tid] = xv;
            Aa[tid] = awR * cb[0] * xv;
            Bb[tid] = awR * (cb[1] + cb[2] * xv);
        }
        __syncthreads();

        // phase 2: masked matvec -> state -> new_output; 10 warps x 8 rows
        {
            float4 xv4 = ((const float4*)xm)[lane];
            float4 o0  = ((const float4*)outs)[lane];
            float4 o1  = ((const float4*)outs)[lane + 32];
            float4 o2  = (lane < 16) ? ((const float4*)outs)[lane + 64]
                                     : make_float4(0.f, 0.f, 0.f, 0.f);
            #pragma unroll
            for (int rr = 0; rr < 8; rr++) {
                int r = wid * 8 + rr;
                const float4* wr = (const float4*)(wx + r * I_);
                const float4* hr = (const float4*)(wh + r * H_);
                float s = dot4r(wr[lane], xv4);
                s += dot4r(hr[lane], o0);
                s += dot4r(hr[lane + 32], o1);
                if (lane < 16) s += dot4r(hr[lane + 64], o2);
                #pragma unroll
                for (int o = 16; o; o >>= 1) s += __shfl_xor_sync(0xffffffffu, s, o);
                if (lane == 0) {
                    int rg = r0 + r;
                    s -= fmaxf(wh[r * H_ + rg], 0.f) * outs[rg];   // remove diagonal
                    float tot = s + bh[r];
                    float ns  = st[r] * (1.f - AX) + AX * tot;
                    st[r] = ns;
                    float no = tanhf(fmaxf(ns, 0.f));
                    nos[r]  = no;
                    newb[rg] = no;
                    hs[(t * B_ + b) * H_ + rg] = no;
                    uint32_t addr = smem_u32(&newb[rg]);
                    #pragma unroll
                    for (uint32_t p = 0; p < 4; p++)
                        if (p != rank) st_cluster_f32(addr, p, no);
                }
            }
        }
        CLUSTER_SYNC();   // new output visible cluster-wide; also full local barrier

        // phase 3: plastic updates (raw weights; relu only in matvec)
        {
            float4* wxv = (float4*)wx;
            int i4 = tid & 31;                       // constant across k (320 % 32 == 0)
            float4 a4 = ((const float4*)Aa)[i4];
            float4 b4 = ((const float4*)Bb)[i4];
            #pragma unroll
            for (int k = 0; k < 8; k++) {
                int f = tid + k * NTHR;
                float nr = nos[f >> 5];
                float4 w = wxv[f];
                w.x = fmaf(w.x, KW, fmaf(nr, b4.x, a4.x));
                w.y = fmaf(w.y, KW, fmaf(nr, b4.y, a4.y));
                w.z = fmaf(w.z, KW, fmaf(nr, b4.z, a4.z));
                w.w = fmaf(w.w, KW, fmaf(nr, b4.w, a4.w));
                wxv[f] = w;
            }
            float4* whv = (float4*)wh;
            int j4 = tid % 80;                       // constant across k (320 % 80 == 0)
            float4 c4 = ((const float4*)Cc)[j4];
            float4 d4 = ((const float4*)Dd)[j4];
            #pragma unroll
            for (int k = 0; k < 20; k++) {
                int f = tid + k * NTHR;
                float nr = nos[f / 80];
                float4 w = whv[f];
                w.x = fmaf(w.x, KW, fmaf(nr, d4.x, c4.x));
                w.y = fmaf(w.y, KW, fmaf(nr, d4.y, c4.y));
                w.z = fmaf(w.z, KW, fmaf(nr, d4.z, c4.z));
                w.w = fmaf(w.w, KW, fmaf(nr, d4.w, c4.w));
                whv[f] = w;
            }
        }
        __syncthreads();
    }
}

// epilogue: out[t,b,o] = sigmoid( sum_{h<256} relu(W_h2o[o,h]) * hs[t,b,h] + b_h2o[o] )
__global__ void __launch_bounds__(256)
out_kernel(const float* __restrict__ hs, const float* __restrict__ W_h2o,
           const float* __restrict__ b_h2o, float* __restrict__ out)
{
    __shared__ float hrow[SIGNB];
    int tb = blockIdx.x;
    const float* h = hs + (size_t)tb * H_;
    if (threadIdx.x < SIGNB) hrow[threadIdx.x] = h[threadIdx.x];
    __syncthreads();
    int wid = threadIdx.x >> 5, lane = threadIdx.x & 31;
    #pragma unroll
    for (int oo = 0; oo < 4; oo++) {
        int o = wid * 4 + oo;
        float s = 0.f;
        #pragma unroll
        for (int k = 0; k < 8; k++) {
            int j = lane + 32 * k;
            s += fmaxf(__ldg(&W_h2o[o * H_ + j]), 0.f) * hrow[j];
        }
        #pragma unroll
        for (int off = 16; off; off >>= 1) s += __shfl_xor_sync(0xffffffffu, s, off);
        if (lane == 0) {
            float z = s + b_h2o[o];
            out[tb * O_ + o] = 1.f / (1.f + expf(-z));
        }
    }
}

extern "C" void kernel_launch(void* const* d_in, const int* in_sizes, int n_in,
                              void* d_out, int out_size)
{
    (void)in_sizes; (void)n_in; (void)out_size;
    const float* x      = (const float*)d_in[0];
    const float* Rs     = (const float*)d_in[1];
    const float* W_x2h  = (const float*)d_in[2];
    const float* W_h2h  = (const float*)d_in[3];
    const float* b_h2h  = (const float*)d_in[4];
    const float* W_h2o  = (const float*)d_in[5];
    const float* b_h2o  = (const float*)d_in[6];
    const float* W_attn = (const float*)d_in[7];
    const float* b_attn = (const float*)d_in[8];
    const float* c_plas = (const float*)d_in[9];

    float* out = (float*)d_out;
    float* hs  = out + (size_t)T_ * B_ * O_;   // hs stored after out in d_out

    cudaFuncSetAttribute(rnn_kernel, cudaFuncAttributeMaxDynamicSharedMemorySize, SMEM_BYTES);

    cudaLaunchConfig_t cfg = {};
    cfg.gridDim  = dim3(B_ * 4, 1, 1);
    cfg.blockDim = dim3(NTHR, 1, 1);
    cfg.dynamicSmemBytes = SMEM_BYTES;
    cfg.stream = 0;
    cudaLaunchAttribute attr[1];
    attr[0].id = cudaLaunchAttributeClusterDimension;
    attr[0].val.clusterDim.x = 4;
    attr[0].val.clusterDim.y = 1;
    attr[0].val.clusterDim.z = 1;
    cfg.attrs = attr;
    cfg.numAttrs = 1;
    cudaLaunchKernelEx(&cfg, rnn_kernel, x, Rs, W_x2h, W_h2h, b_h2h,
                       W_attn, b_attn, c_plas, hs);

    out_kernel<<<T_ * B_, 256>>>(hs, W_h2o, b_h2o, out);
}

// round 2
// speedup vs baseline: 1.2087x; 1.2087x over previous
#include <cuda_runtime.h>
#include <cstdint>

#define T_ 128
#define B_ 32
#define I_ 128
#define H_ 320
#define O_ 32
#define G_ 8
#define HP 80            // hidden rows per CTA (H/4)
#define NTHR 512
#define ROWS_PER_WARP 5  // 80 rows / 16 warps
#define AX 0.2f          // ALPHA_X
#define AW 0.1f          // ALPHA_W
#define KW 0.9f          // 1 - ALPHA_W
#define SIGNB 256        // sign flip / exist cutoff
#define EA_STRIDE 328    // padded row stride for ea (bank-conflict-free)

// ---- shared memory layout (float offsets), total 40960 floats = 160 KB ----
#define OFF_WX    0        // 80*128 = 10240
#define OFF_WH    10240    // 80*320 = 25600
#define OFF_BUF   35840    // 3*320  = 960  (output ring buffer, replicated per CTA)
#define OFF_OUTS  36800    // 320  (sign-applied old output)
#define OFF_XM    37120    // 128
#define OFF_A     37248    // 128
#define OFF_B     37376    // 128
#define OFF_C     37504    // 320
#define OFF_D     37824    // 320
#define OFF_ST    38144    // 80   (state)
#define OFF_BH    38224    // 80   (b_h2h chunk)
#define OFF_EA    38304    // 8*328 = 2624
#define OFF_LG    40928    // 8
#define OFF_AT    40936    // 8
#define OFF_BA    40944    // 8
#define OFF_CB    40952    // 8
#define SMEM_FLOATS 40960
#define SMEM_BYTES (SMEM_FLOATS * 4)

__device__ __forceinline__ uint32_t smem_u32(const void* p) {
    return (uint32_t)__cvta_generic_to_shared(p);
}
__device__ __forceinline__ void st_cluster_f32(uint32_t addr, uint32_t rank, float v) {
    uint32_t ra;
    asm volatile("mapa.shared::cluster.u32 %0, %1, %2;" : "=r"(ra) : "r"(addr), "r"(rank));
    asm volatile("st.shared::cluster.f32 [%0], %1;" :: "r"(ra), "f"(v) : "memory");
}
#define CLUSTER_SYNC() do { \
    asm volatile("barrier.cluster.arrive.aligned;" ::: "memory"); \
    asm volatile("barrier.cluster.wait.aligned;"   ::: "memory"); } while (0)

__device__ __forceinline__ float dot4r(float4 w, float4 v) {
    return fmaxf(w.x, 0.f) * v.x + fmaxf(w.y, 0.f) * v.y +
           fmaxf(w.z, 0.f) * v.z + fmaxf(w.w, 0.f) * v.w;
}
__device__ __forceinline__ float4 upd4(float4 w, float no, float4 a, float4 bq) {
    float4 r;
    r.x = fmaf(w.x, KW, fmaf(no, bq.x, a.x));
    r.y = fmaf(w.y, KW, fmaf(no, bq.y, a.y));
    r.z = fmaf(w.z, KW, fmaf(no, bq.z, a.z));
    r.w = fmaf(w.w, KW, fmaf(no, bq.w, a.w));
    return r;
}

__global__ void __launch_bounds__(NTHR, 1)
rnn_kernel(const float* __restrict__ x, const float* __restrict__ Rs,
           const float* __restrict__ W_x2h, const float* __restrict__ W_h2h,
           const float* __restrict__ b_h2h, const float* __restrict__ W_attn,
           const float* __restrict__ b_attn, const float* __restrict__ c_plas,
           float* __restrict__ hs)
{
    extern __shared__ float sm[];
    float* wx   = sm + OFF_WX;
    float* wh   = sm + OFF_WH;
    float* buf  = sm + OFF_BUF;
    float* outs = sm + OFF_OUTS;
    float* xm   = sm + OFF_XM;
    float* Aa   = sm + OFF_A;
    float* Bb   = sm + OFF_B;
    float* Cc   = sm + OFF_C;
    float* Dd   = sm + OFF_D;
    float* st   = sm + OFF_ST;
    float* bh   = sm + OFF_BH;
    float* ea   = sm + OFF_EA;
    float* lg   = sm + OFF_LG;
    float* at   = sm + OFF_AT;
    float* ba   = sm + OFF_BA;
    float* cb   = sm + OFF_CB;

    const int tid  = threadIdx.x;
    const int lane = tid & 31;
    const int wid  = tid >> 5;
    uint32_t rank; asm("mov.u32 %0, %%cluster_ctarank;" : "=r"(rank));
    const int b  = blockIdx.x >> 2;
    const int r0 = (int)rank * HP;

    // ---------------- init: load plastic weights + constants into SMEM -------------
    #pragma unroll
    for (int k = 0; k < 20; k++) {             // wx: relu(W_x2h), mask_x = 1
        int f = tid + k * NTHR;
        int rg = r0 + (f >> 7);
        int c  = f & 127;
        wx[f] = fmaxf(W_x2h[rg * I_ + c], 0.f);
    }
    #pragma unroll
    for (int k = 0; k < 50; k++) {             // wh: relu * sign, diag zeroed
        int f = tid + k * NTHR;
        int rl = f / H_;
        int c  = f - rl * H_;
        int rg = r0 + rl;
        float v = fmaxf(W_h2h[rg * H_ + c], 0.f);
        v = (c < SIGNB) ? v : -v;
        if (rg == c) v = 0.f;
        wh[f] = v;
    }
    #pragma unroll
    for (int k = 0; k < 5; k++) {              // ew_attn = relu(W_attn) * mask_a (padded stride)
        int f = tid + k * NTHR;
        int g = f / H_;
        int c = f - g * H_;
        if (f < G_ * H_)
            ea[g * EA_STRIDE + c] = (c < SIGNB) ? fmaxf(W_attn[g * H_ + c], 0.f) : 0.f;
    }
    if (tid < HP) { st[tid] = 0.f; bh[tid] = b_h2h[r0 + tid]; }
    if (tid < H_) { buf[tid] = 0.f; buf[tid + H_] = 0.f; buf[tid + 2 * H_] = 0.f; }
    if (tid < 8) ba[tid] = b_attn[tid];
    if (tid < 6) cb[tid] = fabsf(c_plas[tid]);
    __syncthreads();
    CLUSTER_SYNC();

    // prefetched per-step inputs
    float xr   = (tid < I_) ? x[b * I_ + tid] : 0.f;   // x[t=0]
    float rcur = Rs[b];                                 // Rs[t=0]

    // ---------------- time loop ----------------
    for (int t = 0; t < T_; t++) {
        float* oldb = buf + (t % 3) * H_;
        float* newb = buf + ((t + 1) % 3) * H_;
        const float awR = AW * rcur;

        // phase 1a: outs / wh-update column coeffs (tid < 320)
        if (tid < H_) {
            float oj = oldb[tid];
            outs[tid] = (tid < SIGNB) ? oj : -oj;
            Cc[tid] = awR * cb[3] * oj;
            Dd[tid] = awR * (cb[4] + cb[5] * oj);
        }
        // phase 1a': attention logits + softmax entirely in warp 0
        if (wid == 0) {
            int g = lane >> 2, q = lane & 3;
            const float4* er  = (const float4*)(ea + g * EA_STRIDE);
            const float4* ob4 = (const float4*)oldb;
            float s = 0.f;
            #pragma unroll
            for (int k = 0; k < 16; k++) {     // only first 256 cols nonzero
                int j = q + 4 * k;
                float4 e = er[j], o = ob4[j];
                s += e.x * o.x + e.y * o.y + e.z * o.z + e.w * o.w;
            }
            s += __shfl_xor_sync(0xffffffffu, s, 1);
            s += __shfl_xor_sync(0xffffffffu, s, 2);
            if (q == 0) lg[g] = s + ba[g];
            __syncwarp();
            if (lane < 8) {
                float v = lg[lane];
                float m = v;
                #pragma unroll
                for (int o = 4; o; o >>= 1) m = fmaxf(m, __shfl_xor_sync(0xffu, m, o));
                float e = expf(v - m);
                float s2 = e;
                #pragma unroll
                for (int o = 4; o; o >>= 1) s2 += __shfl_xor_sync(0xffu, s2, o);
                at[lane] = e / s2;
            }
        }
        // prefetch Rs for next step (off critical path)
        float rnext = (t + 1 < T_) ? __ldg(&Rs[(t + 1) * B_ + b]) : 0.f;
        __syncthreads();

        // phase 1b: xm + wx-update column coeffs (tid < 128), then prefetch x[t+1]
        float xnew = 0.f;
        if (tid < I_) {
            float xv = xr * at[tid >> 4] * (float)G_;
            xm[tid] = xv;
            Aa[tid] = awR * cb[0] * xv;
            Bb[tid] = awR * (cb[1] + cb[2] * xv);
            if (t + 1 < T_) xnew = __ldg(&x[((t + 1) * B_ + b) * I_ + tid]);
        }
        __syncthreads();

        // phase 2 (fused): masked matvec -> new_output -> in-register plastic update
        {
            const float4* xm4 = (const float4*)xm;
            const float4* os4 = (const float4*)outs;
            const float4* C4  = (const float4*)Cc;
            const float4* D4  = (const float4*)Dd;
            float4 xv4 = xm4[lane];
            float4 o0  = os4[lane];
            float4 o1  = os4[lane + 32];
            float4 o2  = (lane < 16) ? os4[lane + 64] : make_float4(0,0,0,0);
            float4 a4  = ((const float4*)Aa)[lane];
            float4 b4  = ((const float4*)Bb)[lane];
            float4 c0  = C4[lane],      d0 = D4[lane];
            float4 c1  = C4[lane + 32], d1 = D4[lane + 32];
            float4 c2  = make_float4(0,0,0,0), d2 = make_float4(0,0,0,0);
            if (lane < 16) { c2 = C4[lane + 64]; d2 = D4[lane + 64]; }

            #pragma unroll 2
            for (int rr = 0; rr < ROWS_PER_WARP; rr++) {
                int r = wid * ROWS_PER_WARP + rr;
                float4* wr = (float4*)(wx + r * I_);
                float4* hr = (float4*)(wh + r * H_);
                float4 w0 = wr[lane];
                float4 h0 = hr[lane];
                float4 h1 = hr[lane + 32];
                float4 h2 = (lane < 16) ? hr[lane + 64] : make_float4(0,0,0,0);

                float s  = dot4r(w0, xv4) + dot4r(h1, o1);
                float s2 = dot4r(h0, o0);
                if (lane < 16) s2 += dot4r(h2, o2);
                s += s2;
                #pragma unroll
                for (int o = 16; o; o >>= 1) s += __shfl_xor_sync(0xffffffffu, s, o);

                float no;
                if (lane == 0) {
                    int rg = r0 + r;
                    s -= fmaxf(wh[r * H_ + rg], 0.f) * outs[rg];   // remove diagonal
                    float tot = s + bh[r];
                    float ns  = fmaf(st[r], 1.f - AX, AX * tot);
                    st[r] = ns;
                    no = tanhf(fmaxf(ns, 0.f));
                    newb[rg] = no;
                    hs[(t * B_ + b) * H_ + rg] = no;
                    uint32_t addr = smem_u32(&newb[rg]);
                    #pragma unroll
                    for (uint32_t p = 0; p < 4; p++)
                        if (p != rank) st_cluster_f32(addr, p, no);
                }
                no = __shfl_sync(0xffffffffu, no, 0);

                // in-register plastic update, store once
                wr[lane]      = upd4(w0, no, a4, b4);
                hr[lane]      = upd4(h0, no, c0, d0);
                hr[lane + 32] = upd4(h1, no, c1, d1);
                if (lane < 16) hr[lane + 64] = upd4(h2, no, c2, d2);
            }
        }
        CLUSTER_SYNC();   // new output visible cluster-wide; full local barrier too
        rcur = rnext;
        if (tid < I_) xr = xnew;
    }
}

// epilogue: out[t,b,o] = sigmoid( sum_{h<256} relu(W_h2o[o,h]) * hs[t,b,h] + b_h2o[o] )
__global__ void __launch_bounds__(256)
out_kernel(const float* __restrict__ hs, const float* __restrict__ W_h2o,
           const float* __restrict__ b_h2o, float* __restrict__ out)
{
    __shared__ float hrow[SIGNB];
    int tb = blockIdx.x;
    const float* h = hs + (size_t)tb * H_;
    if (threadIdx.x < SIGNB) hrow[threadIdx.x] = h[threadIdx.x];
    __syncthreads();
    int wid = threadIdx.x >> 5, lane = threadIdx.x & 31;
    #pragma unroll
    for (int oo = 0; oo < 4; oo++) {
        int o = wid * 4 + oo;
        float s = 0.f;
        #pragma unroll
        for (int k = 0; k < 8; k++) {
            int j = lane + 32 * k;
            s += fmaxf(__ldg(&W_h2o[o * H_ + j]), 0.f) * hrow[j];
        }
        #pragma unroll
        for (int off = 16; off; off >>= 1) s += __shfl_xor_sync(0xffffffffu, s, off);
        if (lane == 0) {
            float z = s + b_h2o[o];
            out[tb * O_ + o] = 1.f / (1.f + expf(-z));
        }
    }
}

extern "C" void kernel_launch(void* const* d_in, const int* in_sizes, int n_in,
                              void* d_out, int out_size)
{
    (void)in_sizes; (void)n_in; (void)out_size;
    const float* x      = (const float*)d_in[0];
    const float* Rs     = (const float*)d_in[1];
    const float* W_x2h  = (const float*)d_in[2];
    const float* W_h2h  = (const float*)d_in[3];
    const float* b_h2h  = (const float*)d_in[4];
    const float* W_h2o  = (const float*)d_in[5];
    const float* b_h2o  = (const float*)d_in[6];
    const float* W_attn = (const float*)d_in[7];
    const float* b_attn = (const float*)d_in[8];
    const float* c_plas = (const float*)d_in[9];

    float* out = (float*)d_out;
    float* hs  = out + (size_t)T_ * B_ * O_;   // hs stored after out in d_out

    cudaFuncSetAttribute(rnn_kernel, cudaFuncAttributeMaxDynamicSharedMemorySize, SMEM_BYTES);

    cudaLaunchConfig_t cfg = {};
    cfg.gridDim  = dim3(B_ * 4, 1, 1);
    cfg.blockDim = dim3(NTHR, 1, 1);
    cfg.dynamicSmemBytes = SMEM_BYTES;
    cfg.stream = 0;
    cudaLaunchAttribute attr[1];
    attr[0].id = cudaLaunchAttributeClusterDimension;
    attr[0].val.clusterDim.x = 4;
    attr[0].val.clusterDim.y = 1;
    attr[0].val.clusterDim.z = 1;
    cfg.attrs = attr;
    cfg.numAttrs = 1;
    cudaLaunchKernelEx(&cfg, rnn_kernel, x, Rs, W_x2h, W_h2h, b_h2h,
                       W_attn, b_attn, c_plas, hs);

    out_kernel<<<T_ * B_, 256>>>(hs, W_h2o, b_h2o, out);
}

// round 3
// speedup vs baseline: 1.3060x; 1.0805x over previous
#include <cuda_runtime.h>
#include <cstdint>

#define T_ 128
#define B_ 32
#define I_ 128
#define H_ 320
#define O_ 32
#define G_ 8
#define HP 80            // hidden rows per CTA (H/4)
#define NTHR 544         // 16 consumer warps + 1 producer warp
#define RPW 5            // rows per consumer warp
#define AX 0.2f
#define AW 0.1f
#define KW 0.9f
#define SIGNB 256
#define EA_STRIDE 260    // 260 % 32 == 4 -> near-conflict-free

// ---- shared memory layout (float offsets) ----
#define OFF_WX    0        // 80*128 = 10240
#define OFF_WH    10240    // 80*320 = 25600
#define OFF_BUF   35840    // 3*320 = 960 (output ring buffer)
#define OFF_XM    36800    // 128
#define OFF_EA    36928    // 8*260 = 2080
#define SMEM_FLOATS 39008
#define SMEM_BYTES (SMEM_FLOATS * 4)

__device__ __forceinline__ uint32_t smem_u32(const void* p) {
    return (uint32_t)__cvta_generic_to_shared(p);
}
__device__ __forceinline__ void st_cluster_f32(uint32_t addr, uint32_t rank, float v) {
    uint32_t ra;
    asm volatile("mapa.shared::cluster.u32 %0, %1, %2;" : "=r"(ra) : "r"(addr), "r"(rank));
    asm volatile("st.shared::cluster.f32 [%0], %1;" :: "r"(ra), "f"(v) : "memory");
}
#define CLUSTER_SYNC() do { \
    asm volatile("barrier.cluster.arrive.aligned;" ::: "memory"); \
    asm volatile("barrier.cluster.wait.aligned;"   ::: "memory"); } while (0)
#define BAR_ARRIVE(id, cnt) asm volatile("bar.arrive %0, %1;" :: "r"(id), "r"(cnt) : "memory")
#define BAR_SYNC(id, cnt)   asm volatile("bar.sync %0, %1;"   :: "r"(id), "r"(cnt) : "memory")

__device__ __forceinline__ float dot4r(float4 w, float4 v) {
    return fmaxf(w.x, 0.f) * v.x + fmaxf(w.y, 0.f) * v.y +
           fmaxf(w.z, 0.f) * v.z + fmaxf(w.w, 0.f) * v.w;
}
__device__ __forceinline__ float4 upd4(float4 w, float no, float4 a, float4 bq) {
    float4 r;
    r.x = fmaf(w.x, KW, fmaf(no, bq.x, a.x));
    r.y = fmaf(w.y, KW, fmaf(no, bq.y, a.y));
    r.z = fmaf(w.z, KW, fmaf(no, bq.z, a.z));
    r.w = fmaf(w.w, KW, fmaf(no, bq.w, a.w));
    return r;
}

__global__ void __launch_bounds__(NTHR, 1)
rnn_kernel(const float* __restrict__ x, const float* __restrict__ Rs,
           const float* __restrict__ W_x2h, const float* __restrict__ W_h2h,
           const float* __restrict__ b_h2h, const float* __restrict__ W_attn,
           const float* __restrict__ b_attn, const float* __restrict__ c_plas,
           float* __restrict__ hs)
{
    extern __shared__ float sm[];
    float* wx  = sm + OFF_WX;
    float* wh  = sm + OFF_WH;
    float* buf = sm + OFF_BUF;
    float* xms = sm + OFF_XM;
    float* ea  = sm + OFF_EA;

    const int tid  = threadIdx.x;
    const int lane = tid & 31;
    const int wid  = tid >> 5;
    const bool is_prod = (wid == 16);
    uint32_t rank; asm("mov.u32 %0, %%cluster_ctarank;" : "=r"(rank));
    const int b  = blockIdx.x >> 2;
    const int r0 = (int)rank * HP;

    // ---------------- init ----------------
    for (int k = 0; k < 19; k++) {             // wx = relu(W_x2h)
        int f = tid + k * NTHR;
        if (f < HP * I_) {
            int rg = r0 + (f >> 7);
            wx[f] = fmaxf(W_x2h[rg * I_ + (f & 127)], 0.f);
        }
    }
    for (int k = 0; k < 48; k++) {             // wh = relu * sign, diag zeroed
        int f = tid + k * NTHR;
        if (f < HP * H_) {
            int rl = f / H_;
            int c  = f - rl * H_;
            int rg = r0 + rl;
            float v = fmaxf(W_h2h[rg * H_ + c], 0.f);
            v = (c < SIGNB) ? v : -v;
            if (rg == c) v = 0.f;
            wh[f] = v;
        }
    }
    for (int k = 0; k < 4; k++) {              // ea = relu(W_attn), cols < 256 only used
        int f = tid + k * NTHR;
        if (f < G_ * SIGNB) {
            int g = f >> 8;
            int c = f & 255;
            ea[g * EA_STRIDE + c] = fmaxf(W_attn[g * H_ + c], 0.f);
        }
    }
    if (tid < H_) { buf[tid] = 0.f; buf[tid + H_] = 0.f; buf[tid + 2 * H_] = 0.f; }

    // per-thread constants in registers
    const float cb0 = fabsf(__ldg(&c_plas[0]));
    const float cb1 = fabsf(__ldg(&c_plas[1]));
    const float cb2 = fabsf(__ldg(&c_plas[2]));
    const float cb3 = fabsf(__ldg(&c_plas[3]));
    const float cb4 = fabsf(__ldg(&c_plas[4]));
    const float cb5 = fabsf(__ldg(&c_plas[5]));

    float st_r[RPW], bh_r[RPW];
    if (!is_prod) {
        #pragma unroll
        for (int rr = 0; rr < RPW; rr++) {
            st_r[rr] = 0.f;
            bh_r[rr] = __ldg(&b_h2h[r0 + wid * RPW + rr]);
        }
    }
    float ba_r = 0.f;
    float4 xr4 = make_float4(0, 0, 0, 0);
    if (is_prod) {
        ba_r = __ldg(&b_attn[lane & 7]);
        xr4  = ((const float4*)x)[(size_t)b * 32 + lane];   // x[t=0]
    }
    float rcur = __ldg(&Rs[b]);

    __syncthreads();
    CLUSTER_SYNC();

    // ---------------- time loop ----------------
    for (int t = 0; t < T_; t++) {
        float* oldb = buf + (t % 3) * H_;
        float* newb = buf + ((t + 1) % 3) * H_;
        const float awR  = AW * rcur;
        const float rnext = (t + 1 < T_) ? __ldg(&Rs[(t + 1) * B_ + b]) : 0.f;

        if (is_prod) {
            // ---- attention logits + softmax + xm, all in one warp ----
            const int g = lane >> 2, q = lane & 3;
            const float4* er  = (const float4*)(ea + g * EA_STRIDE);
            const float4* ob4 = (const float4*)oldb;
            float s = 0.f;
            #pragma unroll
            for (int k = 0; k < 16; k++) {     // cols 0..255
                int j = q + 4 * k;
                float4 e = er[j], o = ob4[j];
                s += e.x * o.x + e.y * o.y + e.z * o.z + e.w * o.w;
            }
            s += __shfl_xor_sync(0xffffffffu, s, 1);
            s += __shfl_xor_sync(0xffffffffu, s, 2);
            // lane 4g (and its quad) holds logit g
            float v = __shfl_sync(0xffffffffu, s, (lane & 7) << 2) + ba_r;
            float m = v;
            #pragma unroll
            for (int o = 4; o; o >>= 1) m = fmaxf(m, __shfl_xor_sync(0xffffffffu, m, o));
            float e  = expf(v - m);
            float s2 = e;
            #pragma unroll
            for (int o = 4; o; o >>= 1) s2 += __shfl_xor_sync(0xffffffffu, s2, o);
            float atv = e / s2;
            float at4 = __shfl_sync(0xffffffffu, atv, lane >> 2);
            float4 xv;
            xv.x = xr4.x * at4 * (float)G_;
            xv.y = xr4.y * at4 * (float)G_;
            xv.z = xr4.z * at4 * (float)G_;
            xv.w = xr4.w * at4 * (float)G_;
            ((float4*)xms)[lane] = xv;
            if (t + 1 < T_)
                xr4 = ((const float4*)x)[(size_t)((t + 1) * B_ + b) * 32 + lane];
            BAR_ARRIVE(1, NTHR);
        } else {
            // ---- per-warp register prep from oldb ----
            const float4* ob4 = (const float4*)oldb;
            float4 ob0 = ob4[lane];
            float4 ob1 = ob4[lane + 32];
            float4 ob2 = (lane < 16) ? ob4[lane + 64] : make_float4(0, 0, 0, 0);
            float4 o0 = ob0, o1 = ob1;
            float4 o2 = make_float4(-ob2.x, -ob2.y, -ob2.z, -ob2.w);
            const float k3 = awR * cb3;
            float4 c0, c1, c2, d0, d1, d2;
            c0.x = k3 * ob0.x; c0.y = k3 * ob0.y; c0.z = k3 * ob0.z; c0.w = k3 * ob0.w;
            c1.x = k3 * ob1.x; c1.y = k3 * ob1.y; c1.z = k3 * ob1.z; c1.w = k3 * ob1.w;
            c2.x = k3 * ob2.x; c2.y = k3 * ob2.y; c2.z = k3 * ob2.z; c2.w = k3 * ob2.w;
            d0.x = awR * (cb4 + cb5 * ob0.x); d0.y = awR * (cb4 + cb5 * ob0.y);
            d0.z = awR * (cb4 + cb5 * ob0.z); d0.w = awR * (cb4 + cb5 * ob0.w);
            d1.x = awR * (cb4 + cb5 * ob1.x); d1.y = awR * (cb4 + cb5 * ob1.y);
            d1.z = awR * (cb4 + cb5 * ob1.z); d1.w = awR * (cb4 + cb5 * ob1.w);
            d2.x = awR * (cb4 + cb5 * ob2.x); d2.y = awR * (cb4 + cb5 * ob2.y);
            d2.z = awR * (cb4 + cb5 * ob2.z); d2.w = awR * (cb4 + cb5 * ob2.w);

            BAR_SYNC(1, NTHR);                 // wait for xm
            float4 xv4 = ((const float4*)xms)[lane];
            const float k0 = awR * cb0;
            float4 a4, b4;
            a4.x = k0 * xv4.x; a4.y = k0 * xv4.y; a4.z = k0 * xv4.z; a4.w = k0 * xv4.w;
            b4.x = awR * (cb1 + cb2 * xv4.x); b4.y = awR * (cb1 + cb2 * xv4.y);
            b4.z = awR * (cb1 + cb2 * xv4.z); b4.w = awR * (cb1 + cb2 * xv4.w);

            // ---- fused matvec + activation + plastic update ----
            #pragma unroll 2
            for (int rr = 0; rr < RPW; rr++) {
                int r = wid * RPW + rr;
                float4* wr = (float4*)(wx + r * I_);
                float4* hr = (float4*)(wh + r * H_);
                float4 w0 = wr[lane];
                float4 h0 = hr[lane];
                float4 h1 = hr[lane + 32];
                float4 h2 = (lane < 16) ? hr[lane + 64] : make_float4(0, 0, 0, 0);

                float s  = dot4r(w0, xv4) + dot4r(h1, o1);
                float s2 = dot4r(h0, o0);
                if (lane < 16) s2 += dot4r(h2, o2);
                s += s2;
                #pragma unroll
                for (int o = 16; o; o >>= 1) s += __shfl_xor_sync(0xffffffffu, s, o);

                // all lanes: diag correction + activation (identical values)
                int rg = r0 + r;
                float diag = wh[r * H_ + rg];
                float ov = oldb[rg];
                if (rg >= SIGNB) ov = -ov;
                s -= fmaxf(diag, 0.f) * ov;
                float tot = s + bh_r[rr];
                float ns  = fmaf(st_r[rr], 1.f - AX, AX * tot);
                st_r[rr] = ns;
                float no = tanhf(fmaxf(ns, 0.f));

                if (lane == 0) {
                    newb[rg] = no;
                    hs[(size_t)(t * B_ + b) * H_ + rg] = no;
                    uint32_t addr = smem_u32(&newb[rg]);
                    #pragma unroll
                    for (uint32_t p = 0; p < 4; p++)
                        if (p != rank) st_cluster_f32(addr, p, no);
                }

                wr[lane]      = upd4(w0, no, a4, b4);
                hr[lane]      = upd4(h0, no, c0, d0);
                hr[lane + 32] = upd4(h1, no, c1, d1);
                if (lane < 16) hr[lane + 64] = upd4(h2, no, c2, d2);
            }
        }
        CLUSTER_SYNC();
        rcur = rnext;
    }
}

// epilogue: out[t,b,o] = sigmoid( sum_{h<256} relu(W_h2o[o,h]) * hs[t,b,h] + b_h2o[o] )
__global__ void __launch_bounds__(256)
out_kernel(const float* __restrict__ hs, const float* __restrict__ W_h2o,
           const float* __restrict__ b_h2o, float* __restrict__ out)
{
    __shared__ float hrow[SIGNB];
    int tb = blockIdx.x;
    const float* h = hs + (size_t)tb * H_;
    if (threadIdx.x < SIGNB) hrow[threadIdx.x] = h[threadIdx.x];
    __syncthreads();
    int wid = threadIdx.x >> 5, lane = threadIdx.x & 31;
    #pragma unroll
    for (int oo = 0; oo < 4; oo++) {
        int o = wid * 4 + oo;
        float s = 0.f;
        #pragma unroll
        for (int k = 0; k < 8; k++) {
            int j = lane + 32 * k;
            s += fmaxf(__ldg(&W_h2o[o * H_ + j]), 0.f) * hrow[j];
        }
        #pragma unroll
        for (int off = 16; off; off >>= 1) s += __shfl_xor_sync(0xffffffffu, s, off);
        if (lane == 0) {
            float z = s + b_h2o[o];
            out[tb * O_ + o] = 1.f / (1.f + expf(-z));
        }
    }
}

extern "C" void kernel_launch(void* const* d_in, const int* in_sizes, int n_in,
                              void* d_out, int out_size)
{
    (void)in_sizes; (void)n_in; (void)out_size;
    const float* x      = (const float*)d_in[0];
    const float* Rs     = (const float*)d_in[1];
    const float* W_x2h  = (const float*)d_in[2];
    const float* W_h2h  = (const float*)d_in[3];
    const float* b_h2h  = (const float*)d_in[4];
    const float* W_h2o  = (const float*)d_in[5];
    const float* b_h2o  = (const float*)d_in[6];
    const float* W_attn = (const float*)d_in[7];
    const float* b_attn = (const float*)d_in[8];
    const float* c_plas = (const float*)d_in[9];

    float* out = (float*)d_out;
    float* hs  = out + (size_t)T_ * B_ * O_;   // hs stored after out in d_out

    cudaFuncSetAttribute(rnn_kernel, cudaFuncAttributeMaxDynamicSharedMemorySize, SMEM_BYTES);

    cudaLaunchConfig_t cfg = {};
    cfg.gridDim  = dim3(B_ * 4, 1, 1);
    cfg.blockDim = dim3(NTHR, 1, 1);
    cfg.dynamicSmemBytes = SMEM_BYTES;
    cfg.stream = 0;
    cudaLaunchAttribute attr[1];
    attr[0].id = cudaLaunchAttributeClusterDimension;
    attr[0].val.clusterDim.x = 4;
    attr[0].val.clusterDim.y = 1;
    attr[0].val.clusterDim.z = 1;
    cfg.attrs = attr;
    cfg.numAttrs = 1;
    cudaLaunchKernelEx(&cfg, rnn_kernel, x, Rs, W_x2h, W_h2h, b_h2h,
                       W_attn, b_attn, c_plas, hs);

    out_kernel<<<T_ * B_, 256>>>(hs, W_h2o, b_h2o, out);
}